// round 14
// baseline (speedup 1.0000x reference)
#include <cuda_runtime.h>
#include <cuda_bf16.h>
#include <math.h>

// Problem shape (fixed by the reference):
//   q,k,v: [H, N, D] fp32   adj: [H, N, N] fp32   alpha,beta: [H] fp32
//   out:   [H, N, D] fp32
#define HH 8
#define NN 4096
#define DD 64
#define NTHREADS 1024
#define GRID_BLOCKS 256          // single wave (<= 2 CTAs/SM x 152 SMs)
#define ROWS 128                 // rows per block in the general path
#define SLAB4 (ROWS * DD / 4)    // 2048 float4 = block's contiguous slab

// ---------------------------------------------------------------------------
// Math identity:
//   P = softmax(Q K^T * scale + adj)
//   out[h,n,:] = beta[h]*(P[h,n,:] @ V[h]) + (alpha[h] - beta[h]*P[h,n,n])*v[h,n,:]
//
// Block bid owns rows [(bid&31)*128, +128) of head h = bid>>5.
//   beta[h]==0 : out = alpha*v over the slab (exact full answer; the beta-
//                scaled correction term is identically zero).
//   beta[h]!=0 : full-softmax path writes the COMPLETE value
//                b*(P@V) + (a - b*P_rr)*v_r for the slab.
// The v load (one 256-bit LDG per thread, L2::evict_last so v stays resident
// across graph replays) and the alpha/beta loads are issued unconditionally
// before the branch, so no memory latency serializes behind beta.
// ---------------------------------------------------------------------------

// 256-bit load with evict_last (sm_103 requires .v8.b32 for this hint).
__device__ __forceinline__ void ldg_evict_last_f8(const float4* p,
                                                  float4& lo, float4& hi) {
    unsigned r0, r1, r2, r3, r4, r5, r6, r7;
    asm volatile(
        "ld.global.L2::evict_last.v8.b32 {%0,%1,%2,%3,%4,%5,%6,%7}, [%8];"
        : "=r"(r0), "=r"(r1), "=r"(r2), "=r"(r3),
          "=r"(r4), "=r"(r5), "=r"(r6), "=r"(r7)
        : "l"(p));
    lo.x = __uint_as_float(r0); lo.y = __uint_as_float(r1);
    lo.z = __uint_as_float(r2); lo.w = __uint_as_float(r3);
    hi.x = __uint_as_float(r4); hi.y = __uint_as_float(r5);
    hi.z = __uint_as_float(r6); hi.w = __uint_as_float(r7);
}

__global__ void __launch_bounds__(NTHREADS)
fused_adj_attention_kernel(const float* __restrict__ q,
                           const float* __restrict__ k,
                           const float* __restrict__ v,
                           const float* __restrict__ adj,
                           const float* __restrict__ alpha,
                           const float* __restrict__ beta,
                           float* __restrict__ out) {
    const int bid  = blockIdx.x;
    const int tid  = threadIdx.x;
    const int h    = bid >> 5;            // head
    const int row0 = (bid & 31) * ROWS;   // first row of this block's slab

    // ---- issue everything up front: v (256-bit) + alpha + beta ----
    const int base = bid * SLAB4;                       // float4 offset of slab
    const float4* __restrict__ v4 = (const float4*)v + base;
    float4*       __restrict__ o4 = (float4*)out + base;

    float4 t0, t1;
    ldg_evict_last_f8(&v4[tid * 2], t0, t1);   // 32B/thread, warp = 1KB contiguous
    const float a = __ldg(&alpha[h]);
    const float b = __ldg(&beta[h]);

    if (b == 0.0f) {
        // exact: correction term is identically zero -> out = alpha * v
        t0.x *= a; t0.y *= a; t0.z *= a; t0.w *= a;
        t1.x *= a; t1.y *= a; t1.z *= a; t1.w *= a;
        o4[tid * 2]     = t0;
        o4[tid * 2 + 1] = t1;
        return;
    }

    // ---- general path: full softmax, writes complete out values ----
    __shared__ float s[NN];           // 16 KB: scores -> exp weights, one row
    __shared__ float qs[DD];
    __shared__ float red[NTHREADS];   // 4 KB

    const float scale = rsqrtf((float)DD);
    const float* kh = k + (long)h * NN * DD;
    const float* vh = v + (long)h * NN * DD;

    for (int rr = 0; rr < ROWS; rr++) {
        const int r = row0 + rr;
        if (tid < DD) qs[tid] = q[((long)h * NN + r) * DD + tid];
        __syncthreads();

        const float* adjr = adj + ((long)h * NN + r) * NN;

        // scores + running max (4 iters at 1024 threads)
        float lmax = -INFINITY;
        for (int m = tid; m < NN; m += NTHREADS) {
            const float* km = kh + (long)m * DD;
            float dot = 0.f;
            #pragma unroll 16
            for (int d = 0; d < DD; d++) dot = fmaf(qs[d], km[d], dot);
            float val = dot * scale + adjr[m];
            s[m] = val;
            lmax = fmaxf(lmax, val);
        }
        red[tid] = lmax; __syncthreads();
        for (int o = NTHREADS / 2; o > 0; o >>= 1) {
            if (tid < o) red[tid] = fmaxf(red[tid], red[tid + o]);
            __syncthreads();
        }
        const float mx = red[0]; __syncthreads();

        // exp + sum
        float lsum = 0.f;
        for (int m = tid; m < NN; m += NTHREADS) {
            float e = expf(s[m] - mx);
            s[m] = e;
            lsum += e;
        }
        red[tid] = lsum; __syncthreads();
        for (int o = NTHREADS / 2; o > 0; o >>= 1) {
            if (tid < o) red[tid] += red[tid + o];
            __syncthreads();
        }
        const float inv = 1.0f / red[0]; __syncthreads();
        const float prr = s[r] * inv;    // P[r,r]

        // weighted V accumulate: thread t -> dim d = t&63, group g = t>>6 (16)
        const int d = tid & 63, g = tid >> 6;
        float acc = 0.f;
        for (int m = g; m < NN; m += 16) acc += s[m] * vh[(long)m * DD + d];
        red[tid] = acc; __syncthreads();
        if (g == 0) {
            float tot = 0.f;
            #pragma unroll
            for (int j = 0; j < 16; j++) tot += red[d + 64 * j];
            // complete value: b*(P@V) + (a - b*P_rr)*v_r
            out[((long)h * NN + r) * DD + d] =
                b * tot * inv + (a - b * prr) * vh[(long)r * DD + d];
        }
        __syncthreads();
    }
}

extern "C" void kernel_launch(void* const* d_in, const int* in_sizes, int n_in,
                              void* d_out, int out_size) {
    const float* q     = (const float*)d_in[0];
    const float* k     = (const float*)d_in[1];
    const float* v     = (const float*)d_in[2];
    const float* adj   = (const float*)d_in[3];
    const float* alpha = (const float*)d_in[4];
    const float* beta  = (const float*)d_in[5];
    float* out = (float*)d_out;

    fused_adj_attention_kernel<<<GRID_BLOCKS, NTHREADS>>>(q, k, v, adj, alpha, beta, out);
}

// round 15
// speedup vs baseline: 1.0383x; 1.0383x over previous
#include <cuda_runtime.h>
#include <cuda_bf16.h>
#include <math.h>

// Problem shape (fixed by the reference):
//   q,k,v: [H, N, D] fp32   adj: [H, N, N] fp32   alpha,beta: [H] fp32
//   out:   [H, N, D] fp32
#define HH 8
#define NN 4096
#define DD 64
#define NTHREADS 1024
#define GRID_BLOCKS 256          // single wave (<= 2 CTAs/SM x 152 SMs)
#define ROWS 128                 // rows per block in the general path
#define SLAB4 (ROWS * DD / 4)    // 2048 float4 = block's contiguous slab

// ---------------------------------------------------------------------------
// Math identity:
//   P = softmax(Q K^T * scale + adj)
//   out[h,n,:] = beta[h]*(P[h,n,:] @ V[h]) + (alpha[h] - beta[h]*P[h,n,n])*v[h,n,:]
//
// Block bid owns rows [(bid&31)*128, +128) of head h = bid>>5 — a contiguous
// 128KB slab of v/out.
//   beta[h]==0 : out = alpha*v over the slab (exact: the beta-scaled
//                correction term is identically zero).
//   beta[h]!=0 : full-softmax path writes the COMPLETE value
//                b*(P@V) + (a - b*P_rr)*v_r for the slab.
// The two v LDG.128s and the alpha/beta loads are issued unconditionally and
// back-to-back before the branch (no latency serialized behind beta).
// Streaming (.cs) stores for out keep v resident in L2 across graph replays.
// ---------------------------------------------------------------------------

__device__ __forceinline__ void st_stream_f4(float4* p, float4 val) {
    asm volatile("st.global.cs.v4.f32 [%0], {%1,%2,%3,%4};"
                 :: "l"(p), "f"(val.x), "f"(val.y), "f"(val.z), "f"(val.w)
                 : "memory");
}

__global__ void __launch_bounds__(NTHREADS)
fused_adj_attention_kernel(const float* __restrict__ q,
                           const float* __restrict__ k,
                           const float* __restrict__ v,
                           const float* __restrict__ adj,
                           const float* __restrict__ alpha,
                           const float* __restrict__ beta,
                           float* __restrict__ out) {
    const int bid  = blockIdx.x;
    const int tid  = threadIdx.x;
    const int h    = bid >> 5;            // head
    const int row0 = (bid & 31) * ROWS;   // first row of this block's slab

    // ---- issue everything up front: 2x LDG.128 (v) + alpha + beta ----
    const int base = bid * SLAB4;                       // float4 offset of slab
    const float4* __restrict__ v4 = (const float4*)v + base;
    float4*       __restrict__ o4 = (float4*)out + base;

    float4 t0 = v4[tid];                  // independent, batched by ptxas
    float4 t1 = v4[tid + NTHREADS];
    const float a = __ldg(&alpha[h]);
    const float b = __ldg(&beta[h]);

    if (b == 0.0f) {
        // exact: correction term is identically zero -> out = alpha * v
        t0.x *= a; t0.y *= a; t0.z *= a; t0.w *= a;
        t1.x *= a; t1.y *= a; t1.z *= a; t1.w *= a;
        st_stream_f4(&o4[tid], t0);
        st_stream_f4(&o4[tid + NTHREADS], t1);
        return;
    }

    // ---- general path: full softmax, writes complete out values ----
    __shared__ float s[NN];           // 16 KB: scores -> exp weights, one row
    __shared__ float qs[DD];
    __shared__ float red[NTHREADS];   // 4 KB

    const float scale = rsqrtf((float)DD);
    const float* kh = k + (long)h * NN * DD;
    const float* vh = v + (long)h * NN * DD;

    for (int rr = 0; rr < ROWS; rr++) {
        const int r = row0 + rr;
        if (tid < DD) qs[tid] = q[((long)h * NN + r) * DD + tid];
        __syncthreads();

        const float* adjr = adj + ((long)h * NN + r) * NN;

        // scores + running max (4 iters at 1024 threads)
        float lmax = -INFINITY;
        for (int m = tid; m < NN; m += NTHREADS) {
            const float* km = kh + (long)m * DD;
            float dot = 0.f;
            #pragma unroll 16
            for (int d = 0; d < DD; d++) dot = fmaf(qs[d], km[d], dot);
            float val = dot * scale + adjr[m];
            s[m] = val;
            lmax = fmaxf(lmax, val);
        }
        red[tid] = lmax; __syncthreads();
        for (int o = NTHREADS / 2; o > 0; o >>= 1) {
            if (tid < o) red[tid] = fmaxf(red[tid], red[tid + o]);
            __syncthreads();
        }
        const float mx = red[0]; __syncthreads();

        // exp + sum
        float lsum = 0.f;
        for (int m = tid; m < NN; m += NTHREADS) {
            float e = expf(s[m] - mx);
            s[m] = e;
            lsum += e;
        }
        red[tid] = lsum; __syncthreads();
        for (int o = NTHREADS / 2; o > 0; o >>= 1) {
            if (tid < o) red[tid] += red[tid + o];
            __syncthreads();
        }
        const float inv = 1.0f / red[0]; __syncthreads();
        const float prr = s[r] * inv;    // P[r,r]

        // weighted V accumulate: thread t -> dim d = t&63, group g = t>>6 (16)
        const int d = tid & 63, g = tid >> 6;
        float acc = 0.f;
        for (int m = g; m < NN; m += 16) acc += s[m] * vh[(long)m * DD + d];
        red[tid] = acc; __syncthreads();
        if (g == 0) {
            float tot = 0.f;
            #pragma unroll
            for (int j = 0; j < 16; j++) tot += red[d + 64 * j];
            // complete value: b*(P@V) + (a - b*P_rr)*v_r
            out[((long)h * NN + r) * DD + d] =
                b * tot * inv + (a - b * prr) * vh[(long)r * DD + d];
        }
        __syncthreads();
    }
}

extern "C" void kernel_launch(void* const* d_in, const int* in_sizes, int n_in,
                              void* d_out, int out_size) {
    const float* q     = (const float*)d_in[0];
    const float* k     = (const float*)d_in[1];
    const float* v     = (const float*)d_in[2];
    const float* adj   = (const float*)d_in[3];
    const float* alpha = (const float*)d_in[4];
    const float* beta  = (const float*)d_in[5];
    float* out = (float*)d_out;

    fused_adj_attention_kernel<<<GRID_BLOCKS, NTHREADS>>>(q, k, v, adj, alpha, beta, out);
}

// round 16
// speedup vs baseline: 1.2605x; 1.2140x over previous
#include <cuda_runtime.h>
#include <cuda_bf16.h>
#include <math.h>

// Problem shape (fixed by the reference):
//   q,k,v: [H, N, D] fp32   adj: [H, N, N] fp32   alpha,beta: [H] fp32
//   out:   [H, N, D] fp32
#define HH 8
#define NN 4096
#define DD 64
#define NTHREADS 1024
#define GRID_BLOCKS 256                            // single wave, 2 CTAs/SM
#define ROWS (NN * HH / GRID_BLOCKS)               // 128 rows/block (general path)
#define TOTAL4 (HH * NN * DD / 4)                  // 524288 float4 elements
#define COPY_STRIDE (GRID_BLOCKS * NTHREADS)       // 262144
#define COPY_ITERS (TOTAL4 / COPY_STRIDE)          // 2

// ---------------------------------------------------------------------------
// Math identity:
//   P = softmax(Q K^T * scale + adj)
//   out[h,n,:] = beta[h]*(P[h,n,:] @ V[h]) + (alpha[h] - beta[h]*P[h,n,n])*v[h,n,:]
//
// Race-free phase split:
//   phase 1 (flat copy, loads issued unconditionally/batched): out = alpha*v
//           ONLY for heads with beta==0 (for those heads this is the exact
//           full answer; the beta-scaled correction is identically zero).
//           Streaming (.cs) stores keep v L2-resident across graph replays.
//   phase 2 (per-row-slab, only if beta[h] != 0): writes the COMPLETE value
//           b*(P@V) + (a - b*P_rr)*v_r. No +=, no cross-block ordering.
// Each output element is written by exactly one phase -> deterministic.
// ---------------------------------------------------------------------------

__device__ __forceinline__ void st_stream_f4(float4* p, float4 val) {
    asm volatile("st.global.cs.v4.f32 [%0], {%1,%2,%3,%4};"
                 :: "l"(p), "f"(val.x), "f"(val.y), "f"(val.z), "f"(val.w)
                 : "memory");
}

__global__ void __launch_bounds__(NTHREADS)
fused_adj_attention_kernel(const float* __restrict__ q,
                           const float* __restrict__ k,
                           const float* __restrict__ v,
                           const float* __restrict__ adj,
                           const float* __restrict__ alpha,
                           const float* __restrict__ beta,
                           float* __restrict__ out) {
    const int bid = blockIdx.x;
    const int tid = threadIdx.x;

    // ---- phase 1: flat copy out = alpha*v (beta==0 heads) ----
    {
        const int i0 = bid * NTHREADS + tid;
        const float4* __restrict__ v4 = (const float4*)v;
        float4*       __restrict__ o4 = (float4*)out;

        float4 t[COPY_ITERS];
        float  a[COPY_ITERS];
        bool   wr[COPY_ITERS];
        #pragma unroll
        for (int j = 0; j < COPY_ITERS; j++) {
            const int i = i0 + j * COPY_STRIDE;
            t[j] = v4[i];                           // batched independent LDG.128
            const int h = i >> 16;                  // i / (N*D/4) = i / 65536
            a[j]  = __ldg(&alpha[h]);
            wr[j] = (__ldg(&beta[h]) == 0.0f);
        }
        #pragma unroll
        for (int j = 0; j < COPY_ITERS; j++) {
            if (wr[j]) {
                const int i = i0 + j * COPY_STRIDE;
                float4 r = t[j];
                r.x *= a[j]; r.y *= a[j]; r.z *= a[j]; r.w *= a[j];
                st_stream_f4(&((float4*)out)[i], r);  // evict-first: keep v in L2
            }
        }
        (void)o4;
    }

    // block -> (head, row slab) for the general path: 32 blocks per head
    const int h    = bid >> 5;
    const int row0 = (bid & 31) * ROWS;

    const float b = __ldg(&beta[h]);
    if (b == 0.0f) return;   // exact: correction term is identically zero

    // ---- phase 2: full-softmax path, writes complete out values ----
    __shared__ float s[NN];           // 16 KB: scores -> exp weights, one row
    __shared__ float qs[DD];
    __shared__ float red[NTHREADS];   // 4 KB

    const float a     = __ldg(&alpha[h]);
    const float scale = rsqrtf((float)DD);
    const float* kh = k + (long)h * NN * DD;
    const float* vh = v + (long)h * NN * DD;

    for (int rr = 0; rr < ROWS; rr++) {
        const int r = row0 + rr;
        if (tid < DD) qs[tid] = q[((long)h * NN + r) * DD + tid];
        __syncthreads();

        const float* adjr = adj + ((long)h * NN + r) * NN;

        // scores + running max (4 iters at 1024 threads)
        float lmax = -INFINITY;
        for (int m = tid; m < NN; m += NTHREADS) {
            const float* km = kh + (long)m * DD;
            float dot = 0.f;
            #pragma unroll 16
            for (int d = 0; d < DD; d++) dot = fmaf(qs[d], km[d], dot);
            float val = dot * scale + adjr[m];
            s[m] = val;
            lmax = fmaxf(lmax, val);
        }
        red[tid] = lmax; __syncthreads();
        for (int o = NTHREADS / 2; o > 0; o >>= 1) {
            if (tid < o) red[tid] = fmaxf(red[tid], red[tid + o]);
            __syncthreads();
        }
        const float mx = red[0]; __syncthreads();

        // exp + sum
        float lsum = 0.f;
        for (int m = tid; m < NN; m += NTHREADS) {
            float e = expf(s[m] - mx);
            s[m] = e;
            lsum += e;
        }
        red[tid] = lsum; __syncthreads();
        for (int o = NTHREADS / 2; o > 0; o >>= 1) {
            if (tid < o) red[tid] += red[tid + o];
            __syncthreads();
        }
        const float inv = 1.0f / red[0]; __syncthreads();
        const float prr = s[r] * inv;    // P[r,r]

        // weighted V accumulate: thread t -> dim d = t&63, group g = t>>6 (16)
        const int d = tid & 63, g = tid >> 6;
        float acc = 0.f;
        for (int m = g; m < NN; m += 16) acc += s[m] * vh[(long)m * DD + d];
        red[tid] = acc; __syncthreads();
        if (g == 0) {
            float tot = 0.f;
            #pragma unroll
            for (int j = 0; j < 16; j++) tot += red[d + 64 * j];
            // complete value: b*(P@V) + (a - b*P_rr)*v_r
            out[((long)h * NN + r) * DD + d] =
                b * tot * inv + (a - b * prr) * vh[(long)r * DD + d];
        }
        __syncthreads();
    }
}

extern "C" void kernel_launch(void* const* d_in, const int* in_sizes, int n_in,
                              void* d_out, int out_size) {
    const float* q     = (const float*)d_in[0];
    const float* k     = (const float*)d_in[1];
    const float* v     = (const float*)d_in[2];
    const float* adj   = (const float*)d_in[3];
    const float* alpha = (const float*)d_in[4];
    const float* beta  = (const float*)d_in[5];
    float* out = (float*)d_out;

    fused_adj_attention_kernel<<<GRID_BLOCKS, NTHREADS>>>(q, k, v, adj, alpha, beta, out);
}